// round 7
// baseline (speedup 1.0000x reference)
#include <cuda_runtime.h>

#define N_   16
#define C_   512
#define H_   64
#define W_   64
#define GRP  4
#define CG   128
#define MIP  16
#define EPS_ 1e-5f

// Scratch (allocation-free): pooled rows/cols and gate vectors.
__device__ float g_gh[N_ * C_ * H_];   // [n][ch][h]  mean over w
__device__ float g_gw[N_ * C_ * W_];   // [n][ch][w]  mean over h
__device__ float g_ah[N_ * C_ * H_];   // sigmoid gate along h
__device__ float g_aw[N_ * C_ * W_];   // sigmoid gate along w

// ---------------------------------------------------------------------------
// Kernel 1: per-(n,ch) 64x64 tile -> row means (gh) and col means (gw).
// ---------------------------------------------------------------------------
__global__ __launch_bounds__(256) void pool_kernel(const float* __restrict__ x) {
    __shared__ float xs[64 * 65];
    const int img = blockIdx.x;                 // n*512 + ch
    const float4* __restrict__ xp = (const float4*)(x + (size_t)img * 4096);
    const int tid = threadIdx.x;

#pragma unroll
    for (int k = 0; k < 4; k++) {
        int idx4 = k * 256 + tid;
        float4 v = xp[idx4];
        int f = idx4 << 2;
        int h = f >> 6, w = f & 63;
        float* p = &xs[h * 65 + w];
        p[0] = v.x; p[1] = v.y; p[2] = v.z; p[3] = v.w;
    }
    __syncthreads();

    if (tid < 64) {
        float s = 0.f;
#pragma unroll
        for (int i = 0; i < 64; i++) s += xs[tid * 65 + i];
        g_gh[img * 64 + tid] = s * (1.f / 64.f);
    } else if (tid < 128) {
        int w = tid - 64;
        float s = 0.f;
#pragma unroll
        for (int i = 0; i < 64; i++) s += xs[i * 65 + w];
        g_gw[img * 64 + w] = s * (1.f / 64.f);
    }
}

// ---------------------------------------------------------------------------
// Kernel 2: per-(n,g) tiny MLP + BN + hard-swish + two sigmoid gate GEMMs.
// ---------------------------------------------------------------------------
__global__ __launch_bounds__(128) void mlp_kernel(
    const float* __restrict__ W1, const float* __restrict__ b1,
    const float* __restrict__ gamma, const float* __restrict__ beta,
    const float* __restrict__ mean_, const float* __restrict__ var_,
    const float* __restrict__ Wh, const float* __restrict__ bh,
    const float* __restrict__ Ww, const float* __restrict__ bw)
{
    __shared__ float W1s[MIP * CG];   // [m][c]
    __shared__ float ys[MIP * 128];   // [m][l]  post-activation
    __shared__ float Whs[CG * MIP];   // [c][m]
    __shared__ float Wws[CG * MIP];   // [c][m]
    __shared__ float bhs[CG], bws[CG];
    __shared__ float scale_s[MIP], shift_s[MIP], b1s[MIP];

    const int tid = threadIdx.x;          // 0..127
    const int blk = blockIdx.x;           // n*4 + g
    const int n = blk >> 2, g = blk & 3;

    for (int i = tid; i < MIP * CG; i += 128) {
        W1s[i] = W1[i];
        Whs[i] = Wh[i];
        Wws[i] = Ww[i];
    }
    bhs[tid] = bh[tid];
    bws[tid] = bw[tid];
    if (tid < MIP) {
        float sc = gamma[tid] * rsqrtf(var_[tid] + EPS_);
        scale_s[tid] = sc;
        shift_s[tid] = beta[tid] - mean_[tid] * sc;
        b1s[tid] = b1[tid];
    }
    __syncthreads();

    // ---- phase 1: y[m][l] = sum_c W1[m][c] * Y[c][l]; thread = l ----
    const int l = tid;
    const float* __restrict__ src = (l < 64)
        ? &g_gh[((size_t)n * C_ + g * CG) * 64 + l]
        : &g_gw[((size_t)n * C_ + g * CG) * 64 + (l - 64)];

    float acc[MIP];
#pragma unroll
    for (int m = 0; m < MIP; m++) acc[m] = 0.f;

#pragma unroll 4
    for (int c = 0; c < CG; c++) {
        float yc = src[c * 64];            // coalesced across the block
#pragma unroll
        for (int m = 0; m < MIP; m++) acc[m] += W1s[m * CG + c] * yc;
    }

#pragma unroll
    for (int m = 0; m < MIP; m++) {
        float v = acc[m] + b1s[m];
        v = v * scale_s[m] + shift_s[m];             // BN (inference)
        float r = fminf(fmaxf(v + 3.f, 0.f), 6.f);   // hard-swish
        ys[m * 128 + l] = v * r * (1.f / 6.f);
    }
    __syncthreads();

    // ---- phase 2: gates. thread = c; ys reads are warp-broadcast ----
    const int c = tid;
    float whr[MIP], wwr[MIP];
#pragma unroll
    for (int m = 0; m < MIP; m++) {
        whr[m] = Whs[c * MIP + m];
        wwr[m] = Wws[c * MIP + m];
    }
    const float bhc = bhs[c], bwc = bws[c];
    const int ch = g * CG + c;
    float* __restrict__ ah_out = &g_ah[((size_t)n * C_ + ch) * 64];
    float* __restrict__ aw_out = &g_aw[((size_t)n * C_ + ch) * 64];

#pragma unroll 2
    for (int l2 = 0; l2 < 64; l2++) {
        float sh = bhc, sw2 = bwc;
#pragma unroll
        for (int m = 0; m < MIP; m++) {
            sh  += whr[m] * ys[m * 128 + l2];
            sw2 += wwr[m] * ys[m * 128 + l2 + 64];
        }
        ah_out[l2] = 1.f / (1.f + __expf(-sh));
        aw_out[l2] = 1.f / (1.f + __expf(-sw2));
    }
}

// ---------------------------------------------------------------------------
// Kernel 3: apply gates + channel shuffle. 4 tiles per CTA:
//   * one coalesced gate stage (512 floats) + single __syncthreads
//   * 16-deep float4 main loop -> MLP_p1 ~ 16, 4x fewer CTA startups
// ---------------------------------------------------------------------------
#define TPC 4   // tiles per CTA
__global__ __launch_bounds__(256) void apply_kernel(const float* __restrict__ x,
                                                    float* __restrict__ out) {
    __shared__ float sAH[TPC * 64];
    __shared__ float sAW[TPC * 64];

    const int tid  = threadIdx.x;
    const int img0 = blockIdx.x * TPC;          // 4 consecutive imgs, same n
    const int n    = img0 >> 9;
    const int ch0  = img0 & 511;

    // stage gates for all 4 tiles (contiguous in g_ah/g_aw)
    sAH[tid] = g_ah[img0 * 64 + tid];
    sAW[tid] = g_aw[img0 * 64 + tid];
    __syncthreads();

    // per-tile shuffled output pointers
    float4* op[TPC];
#pragma unroll
    for (int t = 0; t < TPC; t++) {
        int ch = ch0 + t;
        int fc = (ch & 3) * 128 + (ch >> 2);
        op[t] = (float4*)(out + ((size_t)n * 512 + fc) * 4096);
    }

    const float4* __restrict__ xp = (const float4*)(x + (size_t)img0 * 4096);

#pragma unroll 8
    for (int k = 0; k < 16; k++) {
        int idx4   = k * 256 + tid;          // 0..4095 across the CTA range
        float4 v   = xp[idx4];
        int t      = idx4 >> 10;
        int within = idx4 & 1023;
        int f      = within << 2;
        int h = f >> 6, w = f & 63;
        const float a = sAH[t * 64 + h];
        const float* aw = &sAW[t * 64 + w];
        v.x *= a * aw[0];
        v.y *= a * aw[1];
        v.z *= a * aw[2];
        v.w *= a * aw[3];
        op[t][within] = v;
    }
}

extern "C" void kernel_launch(void* const* d_in, const int* in_sizes, int n_in,
                              void* d_out, int out_size) {
    const float* x     = (const float*)d_in[0];
    const float* W1    = (const float*)d_in[1];
    const float* b1    = (const float*)d_in[2];
    const float* gamma = (const float*)d_in[3];
    const float* beta  = (const float*)d_in[4];
    const float* mean_ = (const float*)d_in[5];
    const float* var_  = (const float*)d_in[6];
    const float* Wh    = (const float*)d_in[7];
    const float* bh    = (const float*)d_in[8];
    const float* Ww    = (const float*)d_in[9];
    const float* bw    = (const float*)d_in[10];
    float* out = (float*)d_out;

    pool_kernel<<<N_ * C_, 256>>>(x);
    mlp_kernel<<<N_ * GRP, 128>>>(W1, b1, gamma, beta, mean_, var_, Wh, bh, Ww, bw);
    apply_kernel<<<(N_ * C_) / TPC, 256>>>(x, out);
}

// round 8
// speedup vs baseline: 1.1250x; 1.1250x over previous
#include <cuda_runtime.h>

#define N_   16
#define C_   512
#define H_   64
#define W_   64
#define GRP  4
#define CG   128
#define MIP  16
#define EPS_ 1e-5f

// Scratch (allocation-free): pooled rows/cols and gate vectors.
__device__ float g_gh[N_ * C_ * H_];   // [n][ch][h]  mean over w
__device__ float g_gw[N_ * C_ * W_];   // [n][ch][w]  mean over h
__device__ float g_ah[N_ * C_ * H_];   // sigmoid gate along h
__device__ float g_aw[N_ * C_ * W_];   // sigmoid gate along w

// ---------------------------------------------------------------------------
// Kernel 1: per-(n,ch) 64x64 tile -> row means (gh) and col means (gw).
// ---------------------------------------------------------------------------
__global__ __launch_bounds__(256) void pool_kernel(const float* __restrict__ x) {
    __shared__ float xs[64 * 65];
    const int img = blockIdx.x;                 // n*512 + ch
    const float4* __restrict__ xp = (const float4*)(x + (size_t)img * 4096);
    const int tid = threadIdx.x;

#pragma unroll
    for (int k = 0; k < 4; k++) {
        int idx4 = k * 256 + tid;
        float4 v = xp[idx4];
        int f = idx4 << 2;
        int h = f >> 6, w = f & 63;
        float* p = &xs[h * 65 + w];
        p[0] = v.x; p[1] = v.y; p[2] = v.z; p[3] = v.w;
    }
    __syncthreads();

    if (tid < 64) {
        float s = 0.f;
#pragma unroll
        for (int i = 0; i < 64; i++) s += xs[tid * 65 + i];
        g_gh[img * 64 + tid] = s * (1.f / 64.f);
    } else if (tid < 128) {
        int w = tid - 64;
        float s = 0.f;
#pragma unroll
        for (int i = 0; i < 64; i++) s += xs[i * 65 + w];
        g_gw[img * 64 + w] = s * (1.f / 64.f);
    }
}

// ---------------------------------------------------------------------------
// Kernel 2: per-(n,g) tiny MLP + BN + hard-swish + two sigmoid gate GEMMs.
// ---------------------------------------------------------------------------
__global__ __launch_bounds__(128) void mlp_kernel(
    const float* __restrict__ W1, const float* __restrict__ b1,
    const float* __restrict__ gamma, const float* __restrict__ beta,
    const float* __restrict__ mean_, const float* __restrict__ var_,
    const float* __restrict__ Wh, const float* __restrict__ bh,
    const float* __restrict__ Ww, const float* __restrict__ bw)
{
    __shared__ float W1s[MIP * CG];   // [m][c]
    __shared__ float ys[MIP * 128];   // [m][l]  post-activation
    __shared__ float Whs[CG * MIP];   // [c][m]
    __shared__ float Wws[CG * MIP];   // [c][m]
    __shared__ float bhs[CG], bws[CG];
    __shared__ float scale_s[MIP], shift_s[MIP], b1s[MIP];

    const int tid = threadIdx.x;          // 0..127
    const int blk = blockIdx.x;           // n*4 + g
    const int n = blk >> 2, g = blk & 3;

    for (int i = tid; i < MIP * CG; i += 128) {
        W1s[i] = W1[i];
        Whs[i] = Wh[i];
        Wws[i] = Ww[i];
    }
    bhs[tid] = bh[tid];
    bws[tid] = bw[tid];
    if (tid < MIP) {
        float sc = gamma[tid] * rsqrtf(var_[tid] + EPS_);
        scale_s[tid] = sc;
        shift_s[tid] = beta[tid] - mean_[tid] * sc;
        b1s[tid] = b1[tid];
    }
    __syncthreads();

    // ---- phase 1: y[m][l] = sum_c W1[m][c] * Y[c][l]; thread = l ----
    const int l = tid;
    const float* __restrict__ src = (l < 64)
        ? &g_gh[((size_t)n * C_ + g * CG) * 64 + l]
        : &g_gw[((size_t)n * C_ + g * CG) * 64 + (l - 64)];

    float acc[MIP];
#pragma unroll
    for (int m = 0; m < MIP; m++) acc[m] = 0.f;

#pragma unroll 4
    for (int c = 0; c < CG; c++) {
        float yc = src[c * 64];            // coalesced across the block
#pragma unroll
        for (int m = 0; m < MIP; m++) acc[m] += W1s[m * CG + c] * yc;
    }

#pragma unroll
    for (int m = 0; m < MIP; m++) {
        float v = acc[m] + b1s[m];
        v = v * scale_s[m] + shift_s[m];             // BN (inference)
        float r = fminf(fmaxf(v + 3.f, 0.f), 6.f);   // hard-swish
        ys[m * 128 + l] = v * r * (1.f / 6.f);
    }
    __syncthreads();

    // ---- phase 2: gates. thread = c; ys reads are warp-broadcast ----
    const int c = tid;
    float whr[MIP], wwr[MIP];
#pragma unroll
    for (int m = 0; m < MIP; m++) {
        whr[m] = Whs[c * MIP + m];
        wwr[m] = Wws[c * MIP + m];
    }
    const float bhc = bhs[c], bwc = bws[c];
    const int ch = g * CG + c;
    float* __restrict__ ah_out = &g_ah[((size_t)n * C_ + ch) * 64];
    float* __restrict__ aw_out = &g_aw[((size_t)n * C_ + ch) * 64];

#pragma unroll 2
    for (int l2 = 0; l2 < 64; l2++) {
        float sh = bhc, sw2 = bwc;
#pragma unroll
        for (int m = 0; m < MIP; m++) {
            sh  += whr[m] * ys[m * 128 + l2];
            sw2 += wwr[m] * ys[m * 128 + l2 + 64];
        }
        ah_out[l2] = 1.f / (1.f + __expf(-sh));
        aw_out[l2] = 1.f / (1.f + __expf(-sw2));
    }
}

// ---------------------------------------------------------------------------
// Kernel 3: apply gates + channel shuffle. Barrier-free, no smem:
//   thread geometry: for idx4 = k*256+tid, h = k*16 + tid/16, and
//   w = (tid&15)*4 is the SAME for all k -> one g_aw float4 per thread,
//   4 g_ah scalars (warp-broadcast), 4 x float4 loads, all independent
//   and front-batched. Reversed traversal kept from R3.
// ---------------------------------------------------------------------------
__global__ __launch_bounds__(256) void apply_kernel(const float* __restrict__ x,
                                                    float* __restrict__ out) {
    const int img = (N_ * C_ - 1) - blockIdx.x;   // reversed traversal
    const int n = img >> 9, ch = img & 511;
    const int tid = threadIdx.x;

    const float4* __restrict__ xp = (const float4*)(x + (size_t)img * 4096);

    // front-batched independent loads (9 in flight, no barrier)
    float4 v0 = xp[tid];
    float4 v1 = xp[256 + tid];
    float4 v2 = xp[512 + tid];
    float4 v3 = xp[768 + tid];

    const int hb = tid >> 4;                 // h base: 0..15
    const int w  = (tid & 15) << 2;          // 0,4,...,60 (k-invariant)
    const float4 ws = *(const float4*)(&g_aw[(size_t)img * 64 + w]);
    const float a0 = g_ah[(size_t)img * 64 + hb];
    const float a1 = g_ah[(size_t)img * 64 + hb + 16];
    const float a2 = g_ah[(size_t)img * 64 + hb + 32];
    const float a3 = g_ah[(size_t)img * 64 + hb + 48];

    const int fc = (ch & 3) * 128 + (ch >> 2);   // channel shuffle
    float4* __restrict__ op = (float4*)(out + ((size_t)n * 512 + fc) * 4096);

    v0.x *= a0 * ws.x; v0.y *= a0 * ws.y; v0.z *= a0 * ws.z; v0.w *= a0 * ws.w;
    v1.x *= a1 * ws.x; v1.y *= a1 * ws.y; v1.z *= a1 * ws.z; v1.w *= a1 * ws.w;
    v2.x *= a2 * ws.x; v2.y *= a2 * ws.y; v2.z *= a2 * ws.z; v2.w *= a2 * ws.w;
    v3.x *= a3 * ws.x; v3.y *= a3 * ws.y; v3.z *= a3 * ws.z; v3.w *= a3 * ws.w;

    op[tid]       = v0;
    op[256 + tid] = v1;
    op[512 + tid] = v2;
    op[768 + tid] = v3;
}

extern "C" void kernel_launch(void* const* d_in, const int* in_sizes, int n_in,
                              void* d_out, int out_size) {
    const float* x     = (const float*)d_in[0];
    const float* W1    = (const float*)d_in[1];
    const float* b1    = (const float*)d_in[2];
    const float* gamma = (const float*)d_in[3];
    const float* beta  = (const float*)d_in[4];
    const float* mean_ = (const float*)d_in[5];
    const float* var_  = (const float*)d_in[6];
    const float* Wh    = (const float*)d_in[7];
    const float* bh    = (const float*)d_in[8];
    const float* Ww    = (const float*)d_in[9];
    const float* bw    = (const float*)d_in[10];
    float* out = (float*)d_out;

    pool_kernel<<<N_ * C_, 256>>>(x);
    mlp_kernel<<<N_ * GRP, 128>>>(W1, b1, gamma, beta, mean_, var_, Wh, bh, Ww, bw);
    apply_kernel<<<N_ * C_, 256>>>(x, out);
}

// round 9
// speedup vs baseline: 1.1483x; 1.0207x over previous
#include <cuda_runtime.h>

#define N_   16
#define C_   512
#define H_   64
#define W_   64
#define GRP  4
#define CG   128
#define MIP  16
#define EPS_ 1e-5f

// Scratch (allocation-free): pooled rows/cols and gate vectors.
__device__ float g_gh[N_ * C_ * H_];   // [n][ch][h]  mean over w
__device__ float g_gw[N_ * C_ * W_];   // [n][ch][w]  mean over h
__device__ float g_ah[N_ * C_ * H_];   // sigmoid gate along h
__device__ float g_aw[N_ * C_ * W_];   // sigmoid gate along w

// ---------------------------------------------------------------------------
// Kernel 1: per-(n,ch) 64x64 tile -> row means (gh) and col means (gw).
// Shuffle-based: per thread, w-quad = (tid&15)*4 is k-invariant and
// h = k*16 + tid/16. Row sums via 16-lane butterfly shuffles (no smem);
// col sums via one float4 accumulator + tiny smem reduction.
// ---------------------------------------------------------------------------
__global__ __launch_bounds__(256) void pool_kernel(const float* __restrict__ x) {
    __shared__ float scol[16 * 64];     // [sub][w] partial col sums
    const int img = blockIdx.x;         // n*512 + ch
    const float4* __restrict__ xp = (const float4*)(x + (size_t)img * 4096);
    const int tid = threadIdx.x;
    const int sub = tid >> 4;           // 0..15
    const int w4  = tid & 15;           // w-quad index (fixed over k)

    // front-batched independent loads
    float4 v0 = xp[tid];
    float4 v1 = xp[256 + tid];
    float4 v2 = xp[512 + tid];
    float4 v3 = xp[768 + tid];

    // ---- col partials: accumulate over the 4 h's this thread covers ----
    float4 ac;
    ac.x = v0.x + v1.x + v2.x + v3.x;
    ac.y = v0.y + v1.y + v2.y + v3.y;
    ac.z = v0.z + v1.z + v2.z + v3.z;
    ac.w = v0.w + v1.w + v2.w + v3.w;
    *(float4*)&scol[sub * 64 + w4 * 4] = ac;

    // ---- row sums: horizontal + 16-lane butterfly (lanes share h per k) ----
    float r0 = (v0.x + v0.y) + (v0.z + v0.w);
    float r1 = (v1.x + v1.y) + (v1.z + v1.w);
    float r2 = (v2.x + v2.y) + (v2.z + v2.w);
    float r3 = (v3.x + v3.y) + (v3.z + v3.w);
#pragma unroll
    for (int d = 1; d < 16; d <<= 1) {
        r0 += __shfl_xor_sync(0xffffffffu, r0, d);
        r1 += __shfl_xor_sync(0xffffffffu, r1, d);
        r2 += __shfl_xor_sync(0xffffffffu, r2, d);
        r3 += __shfl_xor_sync(0xffffffffu, r3, d);
    }
    // lane w4==k publishes row k*16+sub
    if (w4 == 0) g_gh[img * 64 + sub]      = r0 * (1.f / 64.f);
    if (w4 == 1) g_gh[img * 64 + 16 + sub] = r1 * (1.f / 64.f);
    if (w4 == 2) g_gh[img * 64 + 32 + sub] = r2 * (1.f / 64.f);
    if (w4 == 3) g_gh[img * 64 + 48 + sub] = r3 * (1.f / 64.f);

    __syncthreads();

    // ---- col finalize: 64 threads, each sums 16 partials (conflict-free) ----
    if (tid < 64) {
        float s0 = 0.f, s1 = 0.f;
#pragma unroll
        for (int s = 0; s < 16; s += 2) {
            s0 += scol[s * 64 + tid];
            s1 += scol[(s + 1) * 64 + tid];
        }
        g_gw[img * 64 + tid] = (s0 + s1) * (1.f / 64.f);
    }
}

// ---------------------------------------------------------------------------
// Kernel 2: per-(n,g) tiny MLP + BN + hard-swish + two sigmoid gate GEMMs.
// ---------------------------------------------------------------------------
__global__ __launch_bounds__(128) void mlp_kernel(
    const float* __restrict__ W1, const float* __restrict__ b1,
    const float* __restrict__ gamma, const float* __restrict__ beta,
    const float* __restrict__ mean_, const float* __restrict__ var_,
    const float* __restrict__ Wh, const float* __restrict__ bh,
    const float* __restrict__ Ww, const float* __restrict__ bw)
{
    __shared__ float W1s[MIP * CG];   // [m][c]
    __shared__ float ys[MIP * 128];   // [m][l]  post-activation
    __shared__ float Whs[CG * MIP];   // [c][m]
    __shared__ float Wws[CG * MIP];   // [c][m]
    __shared__ float bhs[CG], bws[CG];
    __shared__ float scale_s[MIP], shift_s[MIP], b1s[MIP];

    const int tid = threadIdx.x;          // 0..127
    const int blk = blockIdx.x;           // n*4 + g
    const int n = blk >> 2, g = blk & 3;

    for (int i = tid; i < MIP * CG; i += 128) {
        W1s[i] = W1[i];
        Whs[i] = Wh[i];
        Wws[i] = Ww[i];
    }
    bhs[tid] = bh[tid];
    bws[tid] = bw[tid];
    if (tid < MIP) {
        float sc = gamma[tid] * rsqrtf(var_[tid] + EPS_);
        scale_s[tid] = sc;
        shift_s[tid] = beta[tid] - mean_[tid] * sc;
        b1s[tid] = b1[tid];
    }
    __syncthreads();

    // ---- phase 1: y[m][l] = sum_c W1[m][c] * Y[c][l]; thread = l ----
    const int l = tid;
    const float* __restrict__ src = (l < 64)
        ? &g_gh[((size_t)n * C_ + g * CG) * 64 + l]
        : &g_gw[((size_t)n * C_ + g * CG) * 64 + (l - 64)];

    float acc[MIP];
#pragma unroll
    for (int m = 0; m < MIP; m++) acc[m] = 0.f;

#pragma unroll 4
    for (int c = 0; c < CG; c++) {
        float yc = src[c * 64];            // coalesced across the block
#pragma unroll
        for (int m = 0; m < MIP; m++) acc[m] += W1s[m * CG + c] * yc;
    }

#pragma unroll
    for (int m = 0; m < MIP; m++) {
        float v = acc[m] + b1s[m];
        v = v * scale_s[m] + shift_s[m];             // BN (inference)
        float r = fminf(fmaxf(v + 3.f, 0.f), 6.f);   // hard-swish
        ys[m * 128 + l] = v * r * (1.f / 6.f);
    }
    __syncthreads();

    // ---- phase 2: gates. thread = c; ys reads are warp-broadcast ----
    const int c = tid;
    float whr[MIP], wwr[MIP];
#pragma unroll
    for (int m = 0; m < MIP; m++) {
        whr[m] = Whs[c * MIP + m];
        wwr[m] = Wws[c * MIP + m];
    }
    const float bhc = bhs[c], bwc = bws[c];
    const int ch = g * CG + c;
    float* __restrict__ ah_out = &g_ah[((size_t)n * C_ + ch) * 64];
    float* __restrict__ aw_out = &g_aw[((size_t)n * C_ + ch) * 64];

#pragma unroll 2
    for (int l2 = 0; l2 < 64; l2++) {
        float sh = bhc, sw2 = bwc;
#pragma unroll
        for (int m = 0; m < MIP; m++) {
            sh  += whr[m] * ys[m * 128 + l2];
            sw2 += wwr[m] * ys[m * 128 + l2 + 64];
        }
        ah_out[l2] = 1.f / (1.f + __expf(-sh));
        aw_out[l2] = 1.f / (1.f + __expf(-sw2));
    }
}

// ---------------------------------------------------------------------------
// Kernel 3: apply gates + channel shuffle (R3 proven form: reversed order).
// ---------------------------------------------------------------------------
__global__ __launch_bounds__(256) void apply_kernel(const float* __restrict__ x,
                                                    float* __restrict__ out) {
    __shared__ float sa[64], sw[64];
    const int img = (N_ * C_ - 1) - blockIdx.x;   // reversed traversal
    const int n = img >> 9, ch = img & 511;
    const int tid = threadIdx.x;

    if (tid < 64)       sa[tid]      = g_ah[img * 64 + tid];
    else if (tid < 128) sw[tid - 64] = g_aw[img * 64 + (tid - 64)];
    __syncthreads();

    const int fc = (ch & 3) * 128 + (ch >> 2);
    const float4* __restrict__ xp = (const float4*)(x + (size_t)img * 4096);
    float4* __restrict__ op = (float4*)(out + ((size_t)n * 512 + fc) * 4096);

#pragma unroll
    for (int k = 0; k < 4; k++) {
        int idx4 = k * 256 + tid;
        float4 v = xp[idx4];
        int f = idx4 << 2;
        int h = f >> 6, w = f & 63;
        float a = sa[h];
        v.x *= a * sw[w];
        v.y *= a * sw[w + 1];
        v.z *= a * sw[w + 2];
        v.w *= a * sw[w + 3];
        op[idx4] = v;
    }
}

extern "C" void kernel_launch(void* const* d_in, const int* in_sizes, int n_in,
                              void* d_out, int out_size) {
    const float* x     = (const float*)d_in[0];
    const float* W1    = (const float*)d_in[1];
    const float* b1    = (const float*)d_in[2];
    const float* gamma = (const float*)d_in[3];
    const float* beta  = (const float*)d_in[4];
    const float* mean_ = (const float*)d_in[5];
    const float* var_  = (const float*)d_in[6];
    const float* Wh    = (const float*)d_in[7];
    const float* bh    = (const float*)d_in[8];
    const float* Ww    = (const float*)d_in[9];
    const float* bw    = (const float*)d_in[10];
    float* out = (float*)d_out;

    pool_kernel<<<N_ * C_, 256>>>(x);
    mlp_kernel<<<N_ * GRP, 128>>>(W1, b1, gamma, beta, mean_, var_, Wh, bh, Ww, bw);
    apply_kernel<<<N_ * C_, 256>>>(x, out);
}